// round 12
// baseline (speedup 1.0000x reference)
#include <cuda_runtime.h>
#include <math.h>

#define NN 100000
#define EE 1200000
#define FF 64
#define DD 32
#define GG 64
#define NSP 16

typedef unsigned long long u64;

// packed f32x2 helpers (sm_100+; ptxas never auto-generates these)
#define FMA2(d, a, b, c) asm("fma.rn.f32x2 %0, %1, %2, %3;" : "=l"(d) : "l"(a), "l"(b), "l"(c))
#define ADD2(d, a, b)    asm("add.rn.f32x2 %0, %1, %2;"     : "=l"(d) : "l"(a), "l"(b))
#define PACK2(d, s)      asm("mov.b64 %0, {%1, %1};"        : "=l"(d) : "r"(__float_as_uint(s)))
#define UNPACK2(lo, hi, s) asm("mov.b64 {%0, %1}, %2;" : "=r"(lo), "=r"(hi) : "l"(s))

// ---------------- scratch ----------------
__device__ float g_Af[NN * FF];
__device__ float g_Bf[NN * FF];
__device__ float g_As[NN * FF];
__device__ float g_Bs[NN * FF];
__device__ float g_h [NN * FF];   // conv accumulator (init = x or normed h, residual folded)
__device__ float g_p1[GG * NSP * FF];   // stats partials (no atomics, no zeroing)
__device__ float g_p2[GG * NSP * FF];
__device__ float g_alpha[GG * FF];
__device__ float g_beta [GG * FF];
__device__ float g_cnt[GG];
__device__ int   g_use64;

// ---------------- int32/int64 runtime detection ----------------
__global__ void k_detect(const int2* __restrict__ idx) {
    __shared__ int any;
    if (threadIdx.x == 0) any = 0;
    __syncthreads();
    int2 v = idx[threadIdx.x];
    if (v.y != 0) any = 1;
    __syncthreads();
    if (threadIdx.x == 0) g_use64 = (any == 0) ? 1 : 0;
}

__device__ __forceinline__ float lrelu(float y) { return (y >= 0.f) ? y : 0.01f * y; }

// ---------------- node linear: Af,Bf,As,Bs + h init ----------------
// 8 lanes per node, ONE node per thread-slice (j=1), 3 blocks/SM for latency hiding.
// fused=1: input = leaky(alpha*g_h+beta), rewritten into g_h as residual init.
__global__ __launch_bounds__(256, 3) void k_node(
    const float* __restrict__ x,
    const float* __restrict__ Wf, const float* __restrict__ bf,
    const float* __restrict__ Ws, const float* __restrict__ bs,
    int fused, const int* __restrict__ b32, const long long* __restrict__ b64)
{
    const int tid  = threadIdx.x;
    const int lane = tid & 31;
    const int l    = lane & 7;
    const int sub  = lane >> 3;
    const int warp = tid >> 5;
    const int n    = (blockIdx.x * 8 + warp) * 4 + sub;
    const bool act = (n < NN);

    float xa[8];
    if (act) {
        float4* hp = (float4*)(g_h + (size_t)n * FF);
        float4 v0, v1;
        if (!fused) {
            const float4* xp = (const float4*)(x + (size_t)n * FF);
            v0 = xp[l]; v1 = xp[l + 8];
        } else {
            int g = g_use64 ? (int)b64[n] : b32[n];
            float4 h0 = hp[l], h1 = hp[l + 8];
            const float4* al = (const float4*)(g_alpha + g * 64);
            const float4* be = (const float4*)(g_beta  + g * 64);
            float4 a0 = al[l], a1 = al[l + 8], c0 = be[l], c1 = be[l + 8];
            v0.x = lrelu(fmaf(a0.x, h0.x, c0.x)); v0.y = lrelu(fmaf(a0.y, h0.y, c0.y));
            v0.z = lrelu(fmaf(a0.z, h0.z, c0.z)); v0.w = lrelu(fmaf(a0.w, h0.w, c0.w));
            v1.x = lrelu(fmaf(a1.x, h1.x, c1.x)); v1.y = lrelu(fmaf(a1.y, h1.y, c1.y));
            v1.z = lrelu(fmaf(a1.z, h1.z, c1.z)); v1.w = lrelu(fmaf(a1.w, h1.w, c1.w));
        }
        hp[l] = v0; hp[l + 8] = v1;       // residual init
        xa[0]=v0.x; xa[1]=v0.y; xa[2]=v0.z; xa[3]=v0.w;
        xa[4]=v1.x; xa[5]=v1.y; xa[6]=v1.z; xa[7]=v1.w;
    } else {
        #pragma unroll
        for (int t = 0; t < 8; t++) xa[t] = 0.f;
    }

    u64 aAf[4], aBf[4], aAs[4], aBs[4];
    {
        const float* bofs0 = bf + 4 * l;       const float* bofs1 = bf + 32 + 4 * l;
        const float* sofs0 = bs + 4 * l;       const float* sofs1 = bs + 32 + 4 * l;
        asm("mov.b64 %0, {%1, %2};" : "=l"(aAf[0]) : "r"(__float_as_uint(bofs0[0])), "r"(__float_as_uint(bofs0[1])));
        asm("mov.b64 %0, {%1, %2};" : "=l"(aAf[1]) : "r"(__float_as_uint(bofs0[2])), "r"(__float_as_uint(bofs0[3])));
        asm("mov.b64 %0, {%1, %2};" : "=l"(aAf[2]) : "r"(__float_as_uint(bofs1[0])), "r"(__float_as_uint(bofs1[1])));
        asm("mov.b64 %0, {%1, %2};" : "=l"(aAf[3]) : "r"(__float_as_uint(bofs1[2])), "r"(__float_as_uint(bofs1[3])));
        asm("mov.b64 %0, {%1, %2};" : "=l"(aAs[0]) : "r"(__float_as_uint(sofs0[0])), "r"(__float_as_uint(sofs0[1])));
        asm("mov.b64 %0, {%1, %2};" : "=l"(aAs[1]) : "r"(__float_as_uint(sofs0[2])), "r"(__float_as_uint(sofs0[3])));
        asm("mov.b64 %0, {%1, %2};" : "=l"(aAs[2]) : "r"(__float_as_uint(sofs1[0])), "r"(__float_as_uint(sofs1[1])));
        asm("mov.b64 %0, {%1, %2};" : "=l"(aAs[3]) : "r"(__float_as_uint(sofs1[2])), "r"(__float_as_uint(sofs1[3])));
        aBf[0]=aBf[1]=aBf[2]=aBf[3]=0ull;
        aBs[0]=aBs[1]=aBs[2]=aBs[3]=0ull;
    }

    const ulonglong2* WfA = (const ulonglong2*)Wf;            // rows 0..63
    const ulonglong2* WfB = (const ulonglong2*)(Wf + 4096);   // rows 64..127
    const ulonglong2* WsA = (const ulonglong2*)Ws;
    const ulonglong2* WsB = (const ulonglong2*)(Ws + 4096);

    #pragma unroll 4
    for (int k = 0; k < 64; k++) {
        const int src = (lane & 24) | ((k >> 2) & 7);
        ulonglong2 wfa0 = WfA[k * 16 + l],     wfa1 = WfA[k * 16 + 8 + l];
        ulonglong2 wfb0 = WfB[k * 16 + l],     wfb1 = WfB[k * 16 + 8 + l];
        ulonglong2 wsa0 = WsA[k * 16 + l],     wsa1 = WsA[k * 16 + 8 + l];
        ulonglong2 wsb0 = WsB[k * 16 + l],     wsb1 = WsB[k * 16 + 8 + l];
        float xv = __shfl_sync(0xffffffffu, (k < 32) ? xa[k & 3] : xa[4 + (k & 3)], src);
        u64 xv2; PACK2(xv2, xv);
        FMA2(aAf[0], xv2, wfa0.x, aAf[0]);
        FMA2(aAf[1], xv2, wfa0.y, aAf[1]);
        FMA2(aAf[2], xv2, wfa1.x, aAf[2]);
        FMA2(aAf[3], xv2, wfa1.y, aAf[3]);
        FMA2(aBf[0], xv2, wfb0.x, aBf[0]);
        FMA2(aBf[1], xv2, wfb0.y, aBf[1]);
        FMA2(aBf[2], xv2, wfb1.x, aBf[2]);
        FMA2(aBf[3], xv2, wfb1.y, aBf[3]);
        FMA2(aAs[0], xv2, wsa0.x, aAs[0]);
        FMA2(aAs[1], xv2, wsa0.y, aAs[1]);
        FMA2(aAs[2], xv2, wsa1.x, aAs[2]);
        FMA2(aAs[3], xv2, wsa1.y, aAs[3]);
        FMA2(aBs[0], xv2, wsb0.x, aBs[0]);
        FMA2(aBs[1], xv2, wsb0.y, aBs[1]);
        FMA2(aBs[2], xv2, wsb1.x, aBs[2]);
        FMA2(aBs[3], xv2, wsb1.y, aBs[3]);
    }

    if (act) {
        ulonglong2* dAf = (ulonglong2*)(g_Af + (size_t)n * FF);
        ulonglong2* dBf = (ulonglong2*)(g_Bf + (size_t)n * FF);
        ulonglong2* dAs = (ulonglong2*)(g_As + (size_t)n * FF);
        ulonglong2* dBs = (ulonglong2*)(g_Bs + (size_t)n * FF);
        dAf[l] = make_ulonglong2(aAf[0], aAf[1]); dAf[l+8] = make_ulonglong2(aAf[2], aAf[3]);
        dBf[l] = make_ulonglong2(aBf[0], aBf[1]); dBf[l+8] = make_ulonglong2(aBf[2], aBf[3]);
        dAs[l] = make_ulonglong2(aAs[0], aAs[1]); dAs[l+8] = make_ulonglong2(aAs[2], aAs[3]);
        dBs[l] = make_ulonglong2(aBs[0], aBs[1]); dBs[l+8] = make_ulonglong2(aBs[2], aBs[3]);
    }
}

// ---------------- edge kernel (unchanged) ----------------
__device__ __forceinline__ float msgval(float f, float s) {
    float sig = __fdividef(1.f, 1.f + __expf(-f));
    float sp  = fmaxf(s, 0.f) + __logf(1.f + __expf(-fabsf(s)));
    return sig * sp;
}

__global__ __launch_bounds__(256, 2) void k_edge(
    const int* __restrict__ i32, const long long* __restrict__ i64,
    const float* __restrict__ attr,
    const float* __restrict__ Wf, const float* __restrict__ Ws)
{
    __shared__ float sF[2048], sS[2048];
    const int tid = threadIdx.x;
    for (int i = tid; i < 2048; i += 256) { sF[i] = Wf[8192 + i]; sS[i] = Ws[8192 + i]; }
    __syncthreads();

    const int lane = tid & 31;
    const int l    = lane & 7;
    const int sub  = lane >> 3;
    const int warp = tid >> 5;
    const int use64 = g_use64;
    const ulonglong2* sF2 = (const ulonglong2*)sF;
    const ulonglong2* sS2 = (const ulonglong2*)sS;

    const int ebase = blockIdx.x * 128 + warp * 16 + sub;

    int dIdx[4];
    float av[4][4];
    u64 accf[4][4], accs[4][4];

    #pragma unroll
    for (int j = 0; j < 4; j++) {
        const int e = ebase + 4 * j;
        long long s, d;
        if (use64) { s = i64[e]; d = i64[EE + e]; }
        else       { s = i32[e]; d = i32[EE + e]; }
        dIdx[j] = (int)d;

        float4 a = ((const float4*)attr)[(size_t)e * 8 + l];
        av[j][0] = a.x; av[j][1] = a.y; av[j][2] = a.z; av[j][3] = a.w;

        const ulonglong2* pAf = (const ulonglong2*)(g_Af + (size_t)d * FF);
        const ulonglong2* pBf = (const ulonglong2*)(g_Bf + (size_t)s * FF);
        const ulonglong2* pAs = (const ulonglong2*)(g_As + (size_t)d * FF);
        const ulonglong2* pBs = (const ulonglong2*)(g_Bs + (size_t)s * FF);
        ulonglong2 f0 = pAf[l], f1 = pAf[l + 8];
        ulonglong2 g0 = pBf[l], g1 = pBf[l + 8];
        ulonglong2 s0 = pAs[l], s1 = pAs[l + 8];
        ulonglong2 t0 = pBs[l], t1 = pBs[l + 8];
        ADD2(accf[j][0], f0.x, g0.x); ADD2(accf[j][1], f0.y, g0.y);
        ADD2(accf[j][2], f1.x, g1.x); ADD2(accf[j][3], f1.y, g1.y);
        ADD2(accs[j][0], s0.x, t0.x); ADD2(accs[j][1], s0.y, t0.y);
        ADD2(accs[j][2], s1.x, t1.x); ADD2(accs[j][3], s1.y, t1.y);
    }

    #pragma unroll
    for (int k = 0; k < 32; k++) {
        const int src = (lane & 24) | (k >> 2);
        ulonglong2 wf0 = sF2[k * 16 + l];
        ulonglong2 wf1 = sF2[k * 16 + 8 + l];
        ulonglong2 ws0 = sS2[k * 16 + l];
        ulonglong2 ws1 = sS2[k * 16 + 8 + l];
        #pragma unroll
        for (int j = 0; j < 4; j++) {
            float ak = __shfl_sync(0xffffffffu, av[j][k & 3], src);
            u64 ak2; PACK2(ak2, ak);
            FMA2(accf[j][0], ak2, wf0.x, accf[j][0]);
            FMA2(accf[j][1], ak2, wf0.y, accf[j][1]);
            FMA2(accf[j][2], ak2, wf1.x, accf[j][2]);
            FMA2(accf[j][3], ak2, wf1.y, accf[j][3]);
            FMA2(accs[j][0], ak2, ws0.x, accs[j][0]);
            FMA2(accs[j][1], ak2, ws0.y, accs[j][1]);
            FMA2(accs[j][2], ak2, ws1.x, accs[j][2]);
            FMA2(accs[j][3], ak2, ws1.y, accs[j][3]);
        }
    }

    #pragma unroll
    for (int j = 0; j < 4; j++) {
        float ff[8], ss2[8];
        #pragma unroll
        for (int p = 0; p < 4; p++) {
            unsigned int lo, hi;
            UNPACK2(lo, hi, accf[j][p]); ff[2*p] = __uint_as_float(lo); ff[2*p+1] = __uint_as_float(hi);
            UNPACK2(lo, hi, accs[j][p]); ss2[2*p] = __uint_as_float(lo); ss2[2*p+1] = __uint_as_float(hi);
        }
        float4 m0 = make_float4(msgval(ff[0], ss2[0]), msgval(ff[1], ss2[1]),
                                msgval(ff[2], ss2[2]), msgval(ff[3], ss2[3]));
        float4 m1 = make_float4(msgval(ff[4], ss2[4]), msgval(ff[5], ss2[5]),
                                msgval(ff[6], ss2[6]), msgval(ff[7], ss2[7]));
        float4* ph = (float4*)(g_h + (size_t)dIdx[j] * FF);
        atomicAdd(ph + l,     m0);
        atomicAdd(ph + l + 8, m1);
    }
}

// ---------------- graph-norm ----------------
__device__ __forceinline__ long long bget(const int* b32, const long long* b64, int u, int i) {
    return u ? b64[i] : (long long)b32[i];
}

__global__ __launch_bounds__(256) void k_stats(const int* __restrict__ b32,
                                               const long long* __restrict__ b64) {
    const int g = blockIdx.x / NSP;
    const int sp = blockIdx.x % NSP;
    const int u = g_use64;

    int lo = 0, hi = NN;
    while (lo < hi) { int mid = (lo + hi) >> 1; if (bget(b32, b64, u, mid) < (long long)g) lo = mid + 1; else hi = mid; }
    const int s0 = lo;
    hi = NN;
    while (lo < hi) { int mid = (lo + hi) >> 1; if (bget(b32, b64, u, mid) < (long long)(g + 1)) lo = mid + 1; else hi = mid; }
    const int s1 = lo;

    const int len = s1 - s0;
    const int chunk = (len + NSP - 1) / NSP;
    const int a = s0 + sp * chunk;
    const int b = min(a + chunk, s1);

    const int f = threadIdx.x & 63;
    const int j = threadIdx.x >> 6;
    float sA = 0.f, qA = 0.f, sB = 0.f, qB = 0.f;
    int n = a + j;
    for (; n + 4 < b; n += 8) {
        float v = g_h[(size_t)n * FF + f];
        float w = g_h[(size_t)(n + 4) * FF + f];
        sA += v; qA += v * v;
        sB += w; qB += w * w;
    }
    if (n < b) { float v = g_h[(size_t)n * FF + f]; sA += v; qA += v * v; }

    __shared__ float r1[256], r2[256];
    r1[threadIdx.x] = sA + sB; r2[threadIdx.x] = qA + qB;
    __syncthreads();
    if (j == 0) {
        g_p1[(g * NSP + sp) * 64 + f] = r1[f] + r1[64 + f] + r1[128 + f] + r1[192 + f];
        g_p2[(g * NSP + sp) * 64 + f] = r2[f] + r2[64 + f] + r2[128 + f] + r2[192 + f];
    }
    if (sp == 0 && threadIdx.x == 0) g_cnt[g] = (float)len;
}

__global__ void k_prep(const float* __restrict__ gw, const float* __restrict__ gb,
                       const float* __restrict__ gm) {
    int i = blockIdx.x * 256 + threadIdx.x;
    if (i >= GG * FF) return;
    int f = i & 63, g = i >> 6;
    float s1 = 0.f, s2 = 0.f;
    #pragma unroll
    for (int sp = 0; sp < NSP; sp++) {
        s1 += g_p1[(g * NSP + sp) * 64 + f];
        s2 += g_p2[(g * NSP + sp) * 64 + f];
    }
    float c    = fmaxf(g_cnt[g], 1.f);
    float inv  = __fdividef(1.f, c);
    float mean = s1 * inv;
    float ex2  = s2 * inv;
    float sub  = gm[f] * mean;
    float var  = ex2 - 2.f * sub * mean + sub * sub;
    float rstd = rsqrtf(var + 1e-5f);
    float al   = gw[f] * rstd;
    g_alpha[i] = al;
    g_beta[i]  = gb[f] - al * sub;
}

__global__ void k_apply(float* __restrict__ out, const int* __restrict__ b32,
                        const long long* __restrict__ b64) {
    int i = blockIdx.x * 256 + threadIdx.x;
    if (i >= NN * FF) return;
    int n = i >> 6, f = i & 63;
    int g = g_use64 ? (int)b64[n] : b32[n];
    float y = g_alpha[g * 64 + f] * g_h[i] + g_beta[g * 64 + f];
    out[i] = lrelu(y);
}

// ---------------- launch ----------------
extern "C" void kernel_launch(void* const* d_in, const int* in_sizes, int n_in,
                              void* d_out, int out_size) {
    const float* x    = (const float*)d_in[0];
    const void*  idx  = d_in[1];
    const float* attr = (const float*)d_in[2];
    const void*  bat  = d_in[3];
    const float* Wf1 = (const float*)d_in[4];  const float* bf1 = (const float*)d_in[5];
    const float* Ws1 = (const float*)d_in[6];  const float* bs1 = (const float*)d_in[7];
    const float* gw1 = (const float*)d_in[8];  const float* gb1 = (const float*)d_in[9];
    const float* gm1 = (const float*)d_in[10];
    const float* Wf2 = (const float*)d_in[11]; const float* bf2 = (const float*)d_in[12];
    const float* Ws2 = (const float*)d_in[13]; const float* bs2 = (const float*)d_in[14];
    const float* gw2 = (const float*)d_in[15]; const float* gb2 = (const float*)d_in[16];
    const float* gm2 = (const float*)d_in[17];
    float* out = (float*)d_out;

    const int*       i32 = (const int*)idx;
    const long long* i64 = (const long long*)idx;
    const int*       b32 = (const int*)bat;
    const long long* b64 = (const long long*)bat;

    const int NB_NODE = (NN + 31) / 32;      // 32 nodes / block (j=1)
    const int NB_EDGE = EE / 128;            // 9375
    const int NB_ELEM = (NN * FF) / 256;

    k_detect<<<1, 256>>>((const int2*)idx);

    // layer 1
    k_node <<<NB_NODE, 256>>>(x, Wf1, bf1, Ws1, bs1, 0, b32, b64);
    k_edge <<<NB_EDGE, 256>>>(i32, i64, attr, Wf1, Ws1);
    k_stats<<<GG * NSP, 256>>>(b32, b64);
    k_prep <<<16, 256>>>(gw1, gb1, gm1);

    // layer 2 (norm1+leaky applied inside k_node on the fly)
    k_node <<<NB_NODE, 256>>>(nullptr, Wf2, bf2, Ws2, bs2, 1, b32, b64);
    k_edge <<<NB_EDGE, 256>>>(i32, i64, attr, Wf2, Ws2);
    k_stats<<<GG * NSP, 256>>>(b32, b64);
    k_prep <<<16, 256>>>(gw2, gb2, gm2);
    k_apply<<<NB_ELEM, 256>>>(out, b32, b64);
}